// round 16
// baseline (speedup 1.0000x reference)
#include <cuda_runtime.h>
#include <cuda_fp16.h>

#define NV 5
#define NS 4
#define CC 32
#define HH 128
#define WW 160
#define DDEP 48
#define HWSZ (HH*WW)          // 20480
#define DHWSZ (DDEP*HWSZ)     // 983040

// conv tiling
#define HT 4
#define HS 6
#define DT 6
#define DS 8
#define WPH 168               // halves per slab row: 2 halo + 160 + 6 pad
#define CONV_THREADS 160
#define CSPLIT 4
#define CPB (CC/CSPLIT)       // 8 channels per block

// ---------------- scratch ----------------------------------------------------
__device__ float g_rot[NS][9];
__device__ float g_trans[NS][3];
__device__ __half g_feaH[NV*HWSZ*CC];           // (view, h, w, c) fp16, 6.5 MB
__device__ __half g_varH[(size_t)CC*DHWSZ];     // planar (c, d,h,w) fp16, 63 MB
__device__ float g_costp[CSPLIT][DHWSZ];        // partial costs

// ---------------- packed f32x2 helpers --------------------------------------
__device__ __forceinline__ unsigned long long pk2(float lo, float hi) {
    unsigned long long p;
    asm("mov.b64 %0, {%1, %2};" : "=l"(p) : "f"(lo), "f"(hi));
    return p;
}
__device__ __forceinline__ unsigned long long fma2(unsigned long long a,
                                                   unsigned long long b,
                                                   unsigned long long c) {
    unsigned long long d;
    asm("fma.rn.f32x2 %0, %1, %2, %3;" : "=l"(d) : "l"(a), "l"(b), "l"(c));
    return d;
}
__device__ __forceinline__ unsigned long long mul2(unsigned long long a,
                                                   unsigned long long b) {
    unsigned long long d;
    asm("mul.rn.f32x2 %0, %1, %2;" : "=l"(d) : "l"(a), "l"(b));
    return d;
}
__device__ __forceinline__ unsigned long long add2(unsigned long long a,
                                                   unsigned long long b) {
    unsigned long long d;
    asm("add.rn.f32x2 %0, %1, %2;" : "=l"(d) : "l"(a), "l"(b));
    return d;
}
__device__ __forceinline__ void upk2(unsigned long long p, float& lo, float& hi) {
    asm("mov.b64 {%0, %1}, %2;" : "=f"(lo), "=f"(hi) : "l"(p));
}
__device__ __forceinline__ __half2 u2h(unsigned int x) {
    return *reinterpret_cast<__half2*>(&x);
}
// fp16 bilinear for one half2 word; result as packed f32x2
__device__ __forceinline__ unsigned long long interp_word(
    unsigned int a00, unsigned int a01, unsigned int a10, unsigned int a11,
    unsigned int w0,  unsigned int w1,  unsigned int w2,  unsigned int w3)
{
    __half2 v = __hmul2(u2h(a11), u2h(w3));
    v = __hfma2(u2h(a10), u2h(w2), v);
    v = __hfma2(u2h(a01), u2h(w1), v);
    v = __hfma2(u2h(a00), u2h(w0), v);
    float2 f = __half22float2(v);
    return pk2(f.x, f.y);
}

// ---------------- kernel 0: projection setup (1 thread, fp32) ---------------
__global__ void k_setup(const float* __restrict__ pm) {
    if (threadIdx.x != 0 || blockIdx.x != 0) return;
    float fused[NV][16];
    for (int n = 0; n < NV; n++) {
        const float* p0 = pm + n * 32;
        const float* p1 = p0 + 16;
        for (int i = 0; i < 16; i++) fused[n][i] = p0[i];
        for (int i = 0; i < 3; i++)
            for (int j = 0; j < 4; j++) {
                float s = 0.0f;
                for (int k = 0; k < 3; k++) s += p1[i*4+k] * p0[k*4+j];
                fused[n][i*4+j] = s;
            }
    }
    float a[4][8];
    for (int i = 0; i < 4; i++)
        for (int j = 0; j < 4; j++) {
            a[i][j]   = fused[0][i*4+j];
            a[i][j+4] = (i == j) ? 1.0f : 0.0f;
        }
    for (int col = 0; col < 4; col++) {
        int piv = col;
        for (int r = col + 1; r < 4; r++)
            if (fabsf(a[r][col]) > fabsf(a[piv][col])) piv = r;
        if (piv != col)
            for (int j = 0; j < 8; j++) { float t = a[col][j]; a[col][j] = a[piv][j]; a[piv][j] = t; }
        float rd = 1.0f / a[col][col];
        for (int j = 0; j < 8; j++) a[col][j] *= rd;
        for (int r = 0; r < 4; r++) {
            if (r == col) continue;
            float f = a[r][col];
            for (int j = 0; j < 8; j++) a[r][j] -= f * a[col][j];
        }
    }
    float inv[16];
    for (int i = 0; i < 4; i++)
        for (int j = 0; j < 4; j++) inv[i*4+j] = a[i][j+4];

    for (int v = 1; v < NV; v++) {
        float P[16];
        for (int i = 0; i < 4; i++)
            for (int j = 0; j < 4; j++) {
                float s = 0.0f;
                for (int k = 0; k < 4; k++) s += fused[v][i*4+k] * inv[k*4+j];
                P[i*4+j] = s;
            }
        for (int i = 0; i < 3; i++)
            for (int j = 0; j < 3; j++) g_rot[v-1][i*3+j] = P[i*4+j];
        for (int i = 0; i < 3; i++) g_trans[v-1][i] = P[i*4+3];
    }
}

// ---------------- kernel 1: transpose (vectorized) --------------------------
__global__ void __launch_bounds__(1024) k_transpose(const float* __restrict__ f) {
    __shared__ float tile[32][129];
    const int n   = blockIdx.y;
    const int p0  = blockIdx.x * 128;
    const int tid = threadIdx.x;

    {
        int c  = tid >> 5;
        int xg = tid & 31;
        float4 v = *(const float4*)(f + ((size_t)(n*CC + c))*HWSZ + p0 + xg*4);
        float* dst = &tile[c][xg*4];
        dst[0] = v.x; dst[1] = v.y; dst[2] = v.z; dst[3] = v.w;
    }
    __syncthreads();

    {
        int pix = tid >> 3;
        int cg  = tid & 7;
        float a0 = tile[cg*4+0][pix];
        float a1 = tile[cg*4+1][pix];
        float a2 = tile[cg*4+2][pix];
        float a3 = tile[cg*4+3][pix];
        __half2 h0 = __floats2half2_rn(a0, a1);
        __half2 h1 = __floats2half2_rn(a2, a3);
        uint2 u;
        u.x = *reinterpret_cast<unsigned int*>(&h0);
        u.y = *reinterpret_cast<unsigned int*>(&h1);
        *reinterpret_cast<uint2*>(g_feaH + ((size_t)(n*HWSZ) + p0 + pix)*CC + cg*4) = u;
    }
}

// ---------------- kernel 2: warp + variance, 2-view-batched gathers ---------
__global__ void __launch_bounds__(128) k_var(const float* __restrict__ dv) {
    __shared__ int4  s_idx[4][4][32];
    __shared__ uint4 s_wth[4][4][32];   // {w,w} half2 x4 per (point, view)
    __shared__ int   s_hw [4][32];
    __shared__ float s_var[128*33];

    const int tid  = threadIdx.x;
    const int warp = tid >> 5;
    const int lane = tid & 31;
    const int gblock = blockIdx.x * 128;

    // ---- phase 1: per-thread projection descriptors for one point ----
    {
        int g  = gblock + tid;
        int d  = g / HWSZ;
        int hw = g - d * HWSZ;
        int h  = hw / WW;
        int w  = hw - h * WW;
        float fx = (float)w, fy = (float)h;
        float depth = __ldg(dv + d);
        #pragma unroll
        for (int v = 0; v < NS; v++) {
            float r0 = g_rot[v][0], r1 = g_rot[v][1], r2 = g_rot[v][2];
            float r3 = g_rot[v][3], r4 = g_rot[v][4], r5 = g_rot[v][5];
            float r6 = g_rot[v][6], r7 = g_rot[v][7], r8 = g_rot[v][8];
            float t0 = g_trans[v][0], t1 = g_trans[v][1], t2 = g_trans[v][2];
            float rx = r0*fx + r1*fy + r2;
            float ry = r3*fx + r4*fy + r5;
            float rz = r6*fx + r7*fy + r8;
            float X = rx*depth + t0;
            float Y = ry*depth + t1;
            float Z = rz*depth + t2;
            float px = __fdividef(X, Z);
            float py = __fdividef(Y, Z);
            float x0 = floorf(px), y0 = floorf(py);
            float x1 = x0 + 1.0f,  y1 = y0 + 1.0f;
            float wx1 = px - x0, wx0 = 1.0f - wx1;
            float wy1 = py - y0, wy0 = 1.0f - wy1;
            bool vx0 = (x0 >= 0.0f) && (x0 <= (float)(WW-1));
            bool vx1 = (x1 >= 0.0f) && (x1 <= (float)(WW-1));
            bool vy0 = (y0 >= 0.0f) && (y0 <= (float)(HH-1));
            bool vy1 = (y1 >= 0.0f) && (y1 <= (float)(HH-1));
            int cx0 = (int)fminf(fmaxf(x0, 0.0f), (float)(WW-1));
            int cx1 = (int)fminf(fmaxf(x1, 0.0f), (float)(WW-1));
            int cy0 = (int)fminf(fmaxf(y0, 0.0f), (float)(HH-1));
            int cy1 = (int)fminf(fmaxf(y1, 0.0f), (float)(HH-1));
            int4 id;
            id.x = cy0*WW + cx0;
            id.y = cy0*WW + cx1;
            id.z = cy1*WW + cx0;
            id.w = cy1*WW + cx1;
            float w00 = wx0*wy0 * ((vx0 && vy0) ? 1.0f : 0.0f);
            float w01 = wx1*wy0 * ((vx1 && vy0) ? 1.0f : 0.0f);
            float w10 = wx0*wy1 * ((vx0 && vy1) ? 1.0f : 0.0f);
            float w11 = wx1*wy1 * ((vx1 && vy1) ? 1.0f : 0.0f);
            __half2 h0 = __float2half2_rn(w00);
            __half2 h1 = __float2half2_rn(w01);
            __half2 h2 = __float2half2_rn(w10);
            __half2 h3 = __float2half2_rn(w11);
            uint4 wh;
            wh.x = *reinterpret_cast<unsigned int*>(&h0);
            wh.y = *reinterpret_cast<unsigned int*>(&h1);
            wh.z = *reinterpret_cast<unsigned int*>(&h2);
            wh.w = *reinterpret_cast<unsigned int*>(&h3);
            s_idx[warp][v][lane] = id;
            s_wth[warp][v][lane] = wh;
        }
        s_hw[warp][lane] = hw;
    }
    __syncwarp();

    // ---- phase 2: lanes = (cg 0..3 x q 0..7); 8 channels per thread --------
    const int cg = lane & 3;          // uint4 = 8 fp16 channels
    const int q  = lane >> 2;
    const uint4* fH4 = (const uint4*)g_feaH;   // pixel stride = 4 uint4
    const float invN = 1.0f / (float)NV;

    #pragma unroll
    for (int it = 0; it < 4; it++) {
        int pt  = it*8 + q;
        int hw2 = s_hw[warp][pt];
        uint4 rf = fH4[(size_t)hw2*4 + cg];
        unsigned long long s0, s1, s2, s3;
        {
            float2 f;
            f = __half22float2(u2h(rf.x)); s0 = pk2(f.x, f.y);
            f = __half22float2(u2h(rf.y)); s1 = pk2(f.x, f.y);
            f = __half22float2(u2h(rf.z)); s2 = pk2(f.x, f.y);
            f = __half22float2(u2h(rf.w)); s3 = pk2(f.x, f.y);
        }
        unsigned long long q0 = mul2(s0, s0);
        unsigned long long q1 = mul2(s1, s1);
        unsigned long long q2 = mul2(s2, s2);
        unsigned long long q3 = mul2(s3, s3);
        // 2-view batches: 8 corner LDG.128 in flight before any interp
        #pragma unroll
        for (int vp = 0; vp < 2; vp++) {
            const int vA = vp*2, vB = vp*2 + 1;
            int4  idA = s_idx[warp][vA][pt];
            int4  idB = s_idx[warp][vB][pt];
            uint4 whA = s_wth[warp][vA][pt];
            uint4 whB = s_wth[warp][vB][pt];
            const uint4* fvA = fH4 + (size_t)(vA+1)*HWSZ*4;
            const uint4* fvB = fH4 + (size_t)(vB+1)*HWSZ*4;
            // issue all 8 gathers
            uint4 a00 = fvA[(size_t)idA.x*4 + cg];
            uint4 a01 = fvA[(size_t)idA.y*4 + cg];
            uint4 a10 = fvA[(size_t)idA.z*4 + cg];
            uint4 a11 = fvA[(size_t)idA.w*4 + cg];
            uint4 b00 = fvB[(size_t)idB.x*4 + cg];
            uint4 b01 = fvB[(size_t)idB.y*4 + cg];
            uint4 b10 = fvB[(size_t)idB.z*4 + cg];
            uint4 b11 = fvB[(size_t)idB.w*4 + cg];
            // view A
            {
                unsigned long long v0 = interp_word(a00.x, a01.x, a10.x, a11.x, whA.x, whA.y, whA.z, whA.w);
                unsigned long long v1 = interp_word(a00.y, a01.y, a10.y, a11.y, whA.x, whA.y, whA.z, whA.w);
                unsigned long long v2 = interp_word(a00.z, a01.z, a10.z, a11.z, whA.x, whA.y, whA.z, whA.w);
                unsigned long long v3 = interp_word(a00.w, a01.w, a10.w, a11.w, whA.x, whA.y, whA.z, whA.w);
                s0 = add2(s0, v0); q0 = fma2(v0, v0, q0);
                s1 = add2(s1, v1); q1 = fma2(v1, v1, q1);
                s2 = add2(s2, v2); q2 = fma2(v2, v2, q2);
                s3 = add2(s3, v3); q3 = fma2(v3, v3, q3);
            }
            // view B
            {
                unsigned long long v0 = interp_word(b00.x, b01.x, b10.x, b11.x, whB.x, whB.y, whB.z, whB.w);
                unsigned long long v1 = interp_word(b00.y, b01.y, b10.y, b11.y, whB.x, whB.y, whB.z, whB.w);
                unsigned long long v2 = interp_word(b00.z, b01.z, b10.z, b11.z, whB.x, whB.y, whB.z, whB.w);
                unsigned long long v3 = interp_word(b00.w, b01.w, b10.w, b11.w, whB.x, whB.y, whB.z, whB.w);
                s0 = add2(s0, v0); q0 = fma2(v0, v0, q0);
                s1 = add2(s1, v1); q1 = fma2(v1, v1, q1);
                s2 = add2(s2, v2); q2 = fma2(v2, v2, q2);
                s3 = add2(s3, v3); q3 = fma2(v3, v3, q3);
            }
        }
        // finalize 8 channels
        float sa[8], qa[8];
        upk2(s0, sa[0], sa[1]); upk2(s1, sa[2], sa[3]);
        upk2(s2, sa[4], sa[5]); upk2(s3, sa[6], sa[7]);
        upk2(q0, qa[0], qa[1]); upk2(q1, qa[2], qa[3]);
        upk2(q2, qa[4], qa[5]); upk2(q3, qa[6], qa[7]);
        int sbase = (warp*32 + pt)*33 + cg*8;
        #pragma unroll
        for (int j = 0; j < 8; j++) {
            float m = sa[j] * invN;
            s_var[sbase + j] = qa[j]*invN - m*m;
        }
    }
    __syncthreads();

    // ---- planar write (fp16, pixel-pair packed) ----
    {
        const int p  = (tid & 63) * 2;
        const int cb = (tid >> 6) * 16;
        const size_t gb = (size_t)gblock + p;
        #pragma unroll
        for (int j = 0; j < 16; j++) {
            int c = cb + j;
            __half2 hv = __floats2half2_rn(s_var[p*33 + c], s_var[(p+1)*33 + c]);
            *reinterpret_cast<unsigned int*>(g_varH + (size_t)c*DHWSZ + gb) =
                *reinterpret_cast<unsigned int*>(&hv);
        }
    }
}

// ---------------- kernel 3: 3x3x3 conv, fp16 slab (R13 config) --------------
__global__ void __launch_bounds__(CONV_THREADS, 4) k_conv(const float* __restrict__ wgt) {
    __shared__ __half slabH[HS][DS][WPH];           // 16.1 KB
    __shared__ unsigned long long wpk[CPB*27];

    const int tid = threadIdx.x;
    const int h0  = blockIdx.x * HT;
    const int d0  = blockIdx.y * DT;
    const int c0  = blockIdx.z * CPB;
    float* __restrict__ outbuf = g_costp[blockIdx.z];
    const int wg  = tid % 40;
    const int hl  = tid / 40;
    const int w0  = wg * 4;

    for (int i = tid; i < CPB*27; i += CONV_THREADS) {
        float k = __ldg(wgt + c0*27 + i);
        wpk[i] = pk2(k, k);
    }
    for (int i = tid; i < HS*DS; i += CONV_THREADS) {
        int shy = i / DS, sdd = i % DS;
        __half* row = &slabH[shy][sdd][0];
        *reinterpret_cast<unsigned int*>(row)       = 0u;
        *reinterpret_cast<unsigned int*>(row + 162) = 0u;
        *reinterpret_cast<unsigned int*>(row + 164) = 0u;
        *reinterpret_cast<unsigned int*>(row + 166) = 0u;
    }

    unsigned long long A[DT][2];
    #pragma unroll
    for (int od = 0; od < DT; od++) { A[od][0] = 0ull; A[od][1] = 0ull; }

    #pragma unroll 1
    for (int c = 0; c < CPB; c++) {
        __syncthreads();

        const __half* __restrict__ vc = g_varH + (size_t)(c0 + c) * DHWSZ;
        #pragma unroll
        for (int r = 0; r < 6; r++) {
            int idx = r*CONV_THREADS + tid;
            int row = idx / 20;
            int w8  = (idx % 20) * 8;
            int shy = row / DS;
            int sdd = row - shy*DS;
            int dd  = d0 - 1 + sdd;
            int hy  = h0 - 1 + shy;
            uint4 v = make_uint4(0u, 0u, 0u, 0u);
            if (dd >= 0 && dd < DDEP && hy >= 0 && hy < HH)
                v = *(const uint4*)(vc + (size_t)dd*HWSZ + hy*WW + w8);
            unsigned int* dst = reinterpret_cast<unsigned int*>(&slabH[shy][sdd][2 + w8]);
            dst[0] = v.x; dst[1] = v.y; dst[2] = v.z; dst[3] = v.w;
        }
        __syncthreads();

        const unsigned long long* wc = wpk + c*27;
        #pragma unroll
        for (int dy = 0; dy < 3; dy++) {
            unsigned long long k00 = wc[(0*3+dy)*3+0], k01 = wc[(0*3+dy)*3+1], k02 = wc[(0*3+dy)*3+2];
            unsigned long long k10 = wc[(1*3+dy)*3+0], k11 = wc[(1*3+dy)*3+1], k12 = wc[(1*3+dy)*3+2];
            unsigned long long k20 = wc[(2*3+dy)*3+0], k21 = wc[(2*3+dy)*3+1], k22 = wc[(2*3+dy)*3+2];
            const __half* hrow = &slabH[hl + dy][0][0];
            #pragma unroll
            for (int sdd = 0; sdd < DS; sdd++) {
                const __half* col = hrow + sdd*WPH;
                uint2 u0 = *(const uint2*)(col + w0);       // (v-2,v-1),(v0,v1)
                uint2 u1 = *(const uint2*)(col + w0 + 4);   // (v2,v3),(v4,v5)
                float2 fA = __half22float2(u2h(u0.x));
                float2 fB = __half22float2(u2h(u0.y));
                float2 fC = __half22float2(u2h(u1.x));
                float2 fD = __half22float2(u2h(u1.y));
                unsigned long long P0 = pk2(fA.y, fB.x);    // (v-1,v0)
                unsigned long long P1 = pk2(fB.x, fB.y);    // (v0,v1)
                unsigned long long P2 = pk2(fB.y, fC.x);    // (v1,v2)
                unsigned long long P3 = pk2(fC.x, fC.y);    // (v2,v3)
                unsigned long long P4 = pk2(fC.y, fD.x);    // (v3,v4)
                #pragma unroll
                for (int dz = 0; dz < 3; dz++) {
                    int od = sdd - dz;
                    if (od < 0 || od >= DT) continue;
                    unsigned long long q0 = (dz==0) ? k00 : (dz==1) ? k10 : k20;
                    unsigned long long q1 = (dz==0) ? k01 : (dz==1) ? k11 : k21;
                    unsigned long long q2 = (dz==0) ? k02 : (dz==1) ? k12 : k22;
                    A[od][0] = fma2(P0, q0, A[od][0]);
                    A[od][0] = fma2(P1, q1, A[od][0]);
                    A[od][0] = fma2(P2, q2, A[od][0]);
                    A[od][1] = fma2(P2, q0, A[od][1]);
                    A[od][1] = fma2(P3, q1, A[od][1]);
                    A[od][1] = fma2(P4, q2, A[od][1]);
                }
            }
        }
    }

    const int ob = (h0 + hl)*WW + w0;
    #pragma unroll
    for (int od = 0; od < DT; od++) {
        float o0, o1, o2, o3;
        upk2(A[od][0], o0, o1);
        upk2(A[od][1], o2, o3);
        float4 v = make_float4(o0, o1, o2, o3);
        *(float4*)(outbuf + (size_t)(d0 + od)*HWSZ + ob) = v;
    }
}

// ---------------- kernel 4: softmax / depth / confidence --------------------
__global__ void __launch_bounds__(128) k_post(const float* __restrict__ dv,
                                              float* __restrict__ out) {
    int pix = blockIdx.x * 128 + threadIdx.x;
    float p[DDEP];
    float mx = -1e30f;
    #pragma unroll
    for (int d = 0; d < DDEP; d++) {
        size_t o = (size_t)d*HWSZ + pix;
        p[d] = (g_costp[0][o] + g_costp[1][o]) + (g_costp[2][o] + g_costp[3][o]);
        mx = fmaxf(mx, p[d]);
    }
    float s = 0.0f;
    #pragma unroll
    for (int d = 0; d < DDEP; d++) { p[d] = expf(p[d] - mx); s += p[d]; }
    float inv = 1.0f / s;
    float depth = 0.0f, didx = 0.0f;
    #pragma unroll
    for (int d = 0; d < DDEP; d++) {
        float pr = p[d] * inv;
        p[d] = pr;
        depth += pr * __ldg(dv + d);
        didx  += pr * (float)d;
    }
    int di = (int)didx;
    di = min(max(di, 0), DDEP - 1);
    float conf = 0.0f;
    #pragma unroll
    for (int d = 0; d < DDEP; d++) {
        bool inwin = (d >= di - 1) && (d <= di + 2);
        conf += inwin ? p[d] : 0.0f;
    }
    out[pix]        = depth;
    out[HWSZ + pix] = conf;
}

// ---------------- launcher ---------------------------------------------------
extern "C" void kernel_launch(void* const* d_in, const int* in_sizes, int n_in,
                              void* d_out, int out_size) {
    const float* features = nullptr;
    const float* pm       = nullptr;
    const float* dv       = nullptr;
    const float* wgt      = nullptr;
    for (int i = 0; i < n_in; i++) {
        switch (in_sizes[i]) {
            case NV*CC*HWSZ: features = (const float*)d_in[i]; break;
            case 160:        pm       = (const float*)d_in[i]; break;
            case 48:         dv       = (const float*)d_in[i]; break;
            case 864:        wgt      = (const float*)d_in[i]; break;
            default: break;
        }
    }
    if (!features) features = (const float*)d_in[0];
    if (!pm)       pm       = (const float*)d_in[1];
    if (!dv)       dv       = (const float*)d_in[2];
    if (!wgt)      wgt      = (const float*)d_in[3];
    float* out = (float*)d_out;

    k_setup<<<1, 32>>>(pm);
    k_transpose<<<dim3(HWSZ/128, NV), 1024>>>(features);
    k_var<<<DHWSZ/128, 128>>>(dv);
    k_conv<<<dim3(HH/HT, DDEP/DT, CSPLIT), CONV_THREADS>>>(wgt);
    k_post<<<HWSZ/128, 128>>>(dv, out);
}

// round 17
// speedup vs baseline: 1.0027x; 1.0027x over previous
#include <cuda_runtime.h>
#include <cuda_fp16.h>

#define NV 5
#define NS 4
#define CC 32
#define HH 128
#define WW 160
#define DDEP 48
#define HWSZ (HH*WW)          // 20480
#define DHWSZ (DDEP*HWSZ)     // 983040

// conv tiling
#define HT 4
#define HS 6
#define DT 6
#define DS 8
#define WPH 168               // halves per slab row: 2 halo + 160 + 6 pad
#define CONV_THREADS 160
#define CSPLIT 4
#define CPB (CC/CSPLIT)       // 8 channels per block

// ---------------- scratch ----------------------------------------------------
__device__ float g_rot[NS][9];
__device__ float g_trans[NS][3];
__device__ __half g_feaH[NV*HWSZ*CC];           // (view, h, w, c) fp16, 6.5 MB
__device__ __half g_varH[(size_t)CC*DHWSZ];     // planar (c, d,h,w) fp16, 63 MB
__device__ float g_costp[CSPLIT][DHWSZ];        // partial costs

// ---------------- packed f32x2 helpers --------------------------------------
__device__ __forceinline__ unsigned long long pk2(float lo, float hi) {
    unsigned long long p;
    asm("mov.b64 %0, {%1, %2};" : "=l"(p) : "f"(lo), "f"(hi));
    return p;
}
__device__ __forceinline__ unsigned long long fma2(unsigned long long a,
                                                   unsigned long long b,
                                                   unsigned long long c) {
    unsigned long long d;
    asm("fma.rn.f32x2 %0, %1, %2, %3;" : "=l"(d) : "l"(a), "l"(b), "l"(c));
    return d;
}
__device__ __forceinline__ unsigned long long mul2(unsigned long long a,
                                                   unsigned long long b) {
    unsigned long long d;
    asm("mul.rn.f32x2 %0, %1, %2;" : "=l"(d) : "l"(a), "l"(b));
    return d;
}
__device__ __forceinline__ unsigned long long add2(unsigned long long a,
                                                   unsigned long long b) {
    unsigned long long d;
    asm("add.rn.f32x2 %0, %1, %2;" : "=l"(d) : "l"(a), "l"(b));
    return d;
}
__device__ __forceinline__ void upk2(unsigned long long p, float& lo, float& hi) {
    asm("mov.b64 {%0, %1}, %2;" : "=f"(lo), "=f"(hi) : "l"(p));
}
__device__ __forceinline__ __half2 u2h(unsigned int x) {
    return *reinterpret_cast<__half2*>(&x);
}
// fp16 bilinear for one half2 word; result as packed f32x2
__device__ __forceinline__ unsigned long long interp_word(
    unsigned int a00, unsigned int a01, unsigned int a10, unsigned int a11,
    unsigned int w0,  unsigned int w1,  unsigned int w2,  unsigned int w3)
{
    __half2 v = __hmul2(u2h(a11), u2h(w3));
    v = __hfma2(u2h(a10), u2h(w2), v);
    v = __hfma2(u2h(a01), u2h(w1), v);
    v = __hfma2(u2h(a00), u2h(w0), v);
    float2 f = __half22float2(v);
    return pk2(f.x, f.y);
}

// ---------------- kernel 0: projection setup (1 thread, fp32) ---------------
__global__ void k_setup(const float* __restrict__ pm) {
    if (threadIdx.x != 0 || blockIdx.x != 0) return;
    float fused[NV][16];
    for (int n = 0; n < NV; n++) {
        const float* p0 = pm + n * 32;
        const float* p1 = p0 + 16;
        for (int i = 0; i < 16; i++) fused[n][i] = p0[i];
        for (int i = 0; i < 3; i++)
            for (int j = 0; j < 4; j++) {
                float s = 0.0f;
                for (int k = 0; k < 3; k++) s += p1[i*4+k] * p0[k*4+j];
                fused[n][i*4+j] = s;
            }
    }
    float a[4][8];
    for (int i = 0; i < 4; i++)
        for (int j = 0; j < 4; j++) {
            a[i][j]   = fused[0][i*4+j];
            a[i][j+4] = (i == j) ? 1.0f : 0.0f;
        }
    for (int col = 0; col < 4; col++) {
        int piv = col;
        for (int r = col + 1; r < 4; r++)
            if (fabsf(a[r][col]) > fabsf(a[piv][col])) piv = r;
        if (piv != col)
            for (int j = 0; j < 8; j++) { float t = a[col][j]; a[col][j] = a[piv][j]; a[piv][j] = t; }
        float rd = 1.0f / a[col][col];
        for (int j = 0; j < 8; j++) a[col][j] *= rd;
        for (int r = 0; r < 4; r++) {
            if (r == col) continue;
            float f = a[r][col];
            for (int j = 0; j < 8; j++) a[r][j] -= f * a[col][j];
        }
    }
    float inv[16];
    for (int i = 0; i < 4; i++)
        for (int j = 0; j < 4; j++) inv[i*4+j] = a[i][j+4];

    for (int v = 1; v < NV; v++) {
        float P[16];
        for (int i = 0; i < 4; i++)
            for (int j = 0; j < 4; j++) {
                float s = 0.0f;
                for (int k = 0; k < 4; k++) s += fused[v][i*4+k] * inv[k*4+j];
                P[i*4+j] = s;
            }
        for (int i = 0; i < 3; i++)
            for (int j = 0; j < 3; j++) g_rot[v-1][i*3+j] = P[i*4+j];
        for (int i = 0; i < 3; i++) g_trans[v-1][i] = P[i*4+3];
    }
}

// ---------------- kernel 1: transpose (vectorized) --------------------------
__global__ void __launch_bounds__(1024) k_transpose(const float* __restrict__ f) {
    __shared__ float tile[32][129];
    const int n   = blockIdx.y;
    const int p0  = blockIdx.x * 128;
    const int tid = threadIdx.x;

    {
        int c  = tid >> 5;
        int xg = tid & 31;
        float4 v = *(const float4*)(f + ((size_t)(n*CC + c))*HWSZ + p0 + xg*4);
        float* dst = &tile[c][xg*4];
        dst[0] = v.x; dst[1] = v.y; dst[2] = v.z; dst[3] = v.w;
    }
    __syncthreads();

    {
        int pix = tid >> 3;
        int cg  = tid & 7;
        float a0 = tile[cg*4+0][pix];
        float a1 = tile[cg*4+1][pix];
        float a2 = tile[cg*4+2][pix];
        float a3 = tile[cg*4+3][pix];
        __half2 h0 = __floats2half2_rn(a0, a1);
        __half2 h1 = __floats2half2_rn(a2, a3);
        uint2 u;
        u.x = *reinterpret_cast<unsigned int*>(&h0);
        u.y = *reinterpret_cast<unsigned int*>(&h1);
        *reinterpret_cast<uint2*>(g_feaH + ((size_t)(n*HWSZ) + p0 + pix)*CC + cg*4) = u;
    }
}

// ---------------- kernel 2: warp + variance, HFMA2 interp + f32x2 accum -----
__global__ void __launch_bounds__(128) k_var(const float* __restrict__ dv) {
    __shared__ int4  s_idx[4][4][32];
    __shared__ uint4 s_wth[4][4][32];   // {w,w} half2 x4 per (point, view)
    __shared__ int   s_hw [4][32];
    __shared__ float s_var[128*33];

    const int tid  = threadIdx.x;
    const int warp = tid >> 5;
    const int lane = tid & 31;
    const int gblock = blockIdx.x * 128;

    // ---- phase 1: per-thread projection descriptors for one point ----
    {
        int g  = gblock + tid;
        int d  = g / HWSZ;
        int hw = g - d * HWSZ;
        int h  = hw / WW;
        int w  = hw - h * WW;
        float fx = (float)w, fy = (float)h;
        float depth = __ldg(dv + d);
        #pragma unroll
        for (int v = 0; v < NS; v++) {
            float r0 = g_rot[v][0], r1 = g_rot[v][1], r2 = g_rot[v][2];
            float r3 = g_rot[v][3], r4 = g_rot[v][4], r5 = g_rot[v][5];
            float r6 = g_rot[v][6], r7 = g_rot[v][7], r8 = g_rot[v][8];
            float t0 = g_trans[v][0], t1 = g_trans[v][1], t2 = g_trans[v][2];
            float rx = r0*fx + r1*fy + r2;
            float ry = r3*fx + r4*fy + r5;
            float rz = r6*fx + r7*fy + r8;
            float X = rx*depth + t0;
            float Y = ry*depth + t1;
            float Z = rz*depth + t2;
            float px = __fdividef(X, Z);
            float py = __fdividef(Y, Z);
            float x0 = floorf(px), y0 = floorf(py);
            float x1 = x0 + 1.0f,  y1 = y0 + 1.0f;
            float wx1 = px - x0, wx0 = 1.0f - wx1;
            float wy1 = py - y0, wy0 = 1.0f - wy1;
            bool vx0 = (x0 >= 0.0f) && (x0 <= (float)(WW-1));
            bool vx1 = (x1 >= 0.0f) && (x1 <= (float)(WW-1));
            bool vy0 = (y0 >= 0.0f) && (y0 <= (float)(HH-1));
            bool vy1 = (y1 >= 0.0f) && (y1 <= (float)(HH-1));
            int cx0 = (int)fminf(fmaxf(x0, 0.0f), (float)(WW-1));
            int cx1 = (int)fminf(fmaxf(x1, 0.0f), (float)(WW-1));
            int cy0 = (int)fminf(fmaxf(y0, 0.0f), (float)(HH-1));
            int cy1 = (int)fminf(fmaxf(y1, 0.0f), (float)(HH-1));
            int4 id;
            id.x = cy0*WW + cx0;
            id.y = cy0*WW + cx1;
            id.z = cy1*WW + cx0;
            id.w = cy1*WW + cx1;
            float w00 = wx0*wy0 * ((vx0 && vy0) ? 1.0f : 0.0f);
            float w01 = wx1*wy0 * ((vx1 && vy0) ? 1.0f : 0.0f);
            float w10 = wx0*wy1 * ((vx0 && vy1) ? 1.0f : 0.0f);
            float w11 = wx1*wy1 * ((vx1 && vy1) ? 1.0f : 0.0f);
            __half2 h0 = __float2half2_rn(w00);
            __half2 h1 = __float2half2_rn(w01);
            __half2 h2 = __float2half2_rn(w10);
            __half2 h3 = __float2half2_rn(w11);
            uint4 wh;
            wh.x = *reinterpret_cast<unsigned int*>(&h0);
            wh.y = *reinterpret_cast<unsigned int*>(&h1);
            wh.z = *reinterpret_cast<unsigned int*>(&h2);
            wh.w = *reinterpret_cast<unsigned int*>(&h3);
            s_idx[warp][v][lane] = id;
            s_wth[warp][v][lane] = wh;
        }
        s_hw[warp][lane] = hw;
    }
    __syncwarp();

    // ---- phase 2: lanes = (cg 0..3 x q 0..7); 8 channels per thread --------
    const int cg = lane & 3;          // uint4 = 8 fp16 channels
    const int q  = lane >> 2;
    const uint4* fH4 = (const uint4*)g_feaH;   // pixel stride = 4 uint4
    const float invN = 1.0f / (float)NV;

    #pragma unroll
    for (int it = 0; it < 4; it++) {
        int pt  = it*8 + q;
        int hw2 = s_hw[warp][pt];
        uint4 rf = fH4[(size_t)hw2*4 + cg];
        unsigned long long s0, s1, s2, s3;
        {
            float2 f;
            f = __half22float2(u2h(rf.x)); s0 = pk2(f.x, f.y);
            f = __half22float2(u2h(rf.y)); s1 = pk2(f.x, f.y);
            f = __half22float2(u2h(rf.z)); s2 = pk2(f.x, f.y);
            f = __half22float2(u2h(rf.w)); s3 = pk2(f.x, f.y);
        }
        unsigned long long q0 = mul2(s0, s0);
        unsigned long long q1 = mul2(s1, s1);
        unsigned long long q2 = mul2(s2, s2);
        unsigned long long q3 = mul2(s3, s3);
        #pragma unroll
        for (int v = 0; v < NS; v++) {
            int4  id = s_idx[warp][v][pt];
            uint4 wh = s_wth[warp][v][pt];
            const uint4* fv = fH4 + (size_t)(v+1)*HWSZ*4;
            uint4 c00 = fv[(size_t)id.x*4 + cg];
            uint4 c01 = fv[(size_t)id.y*4 + cg];
            uint4 c10 = fv[(size_t)id.z*4 + cg];
            uint4 c11 = fv[(size_t)id.w*4 + cg];
            unsigned long long v0 = interp_word(c00.x, c01.x, c10.x, c11.x, wh.x, wh.y, wh.z, wh.w);
            unsigned long long v1 = interp_word(c00.y, c01.y, c10.y, c11.y, wh.x, wh.y, wh.z, wh.w);
            unsigned long long v2 = interp_word(c00.z, c01.z, c10.z, c11.z, wh.x, wh.y, wh.z, wh.w);
            unsigned long long v3 = interp_word(c00.w, c01.w, c10.w, c11.w, wh.x, wh.y, wh.z, wh.w);
            s0 = add2(s0, v0); q0 = fma2(v0, v0, q0);
            s1 = add2(s1, v1); q1 = fma2(v1, v1, q1);
            s2 = add2(s2, v2); q2 = fma2(v2, v2, q2);
            s3 = add2(s3, v3); q3 = fma2(v3, v3, q3);
        }
        // finalize 8 channels
        float sa[8], qa[8];
        upk2(s0, sa[0], sa[1]); upk2(s1, sa[2], sa[3]);
        upk2(s2, sa[4], sa[5]); upk2(s3, sa[6], sa[7]);
        upk2(q0, qa[0], qa[1]); upk2(q1, qa[2], qa[3]);
        upk2(q2, qa[4], qa[5]); upk2(q3, qa[6], qa[7]);
        int sbase = (warp*32 + pt)*33 + cg*8;
        #pragma unroll
        for (int j = 0; j < 8; j++) {
            float m = sa[j] * invN;
            s_var[sbase + j] = qa[j]*invN - m*m;
        }
    }
    __syncthreads();

    // ---- planar write (fp16, pixel-pair packed) ----
    {
        const int p  = (tid & 63) * 2;
        const int cb = (tid >> 6) * 16;
        const size_t gb = (size_t)gblock + p;
        #pragma unroll
        for (int j = 0; j < 16; j++) {
            int c = cb + j;
            __half2 hv = __floats2half2_rn(s_var[p*33 + c], s_var[(p+1)*33 + c]);
            *reinterpret_cast<unsigned int*>(g_varH + (size_t)c*DHWSZ + gb) =
                *reinterpret_cast<unsigned int*>(&hv);
        }
    }
}

// ---------------- kernel 3: 3x3x3 conv, 2 channels per fill stage -----------
__global__ void __launch_bounds__(CONV_THREADS, 4) k_conv(const float* __restrict__ wgt) {
    __shared__ __half slabH[2][HS][DS][WPH];        // 32.3 KB (2 channels)
    __shared__ unsigned long long wpk[CPB*27];

    const int tid = threadIdx.x;
    const int h0  = blockIdx.x * HT;
    const int d0  = blockIdx.y * DT;
    const int c0  = blockIdx.z * CPB;
    float* __restrict__ outbuf = g_costp[blockIdx.z];
    const int wg  = tid % 40;
    const int hl  = tid / 40;
    const int w0  = wg * 4;

    for (int i = tid; i < CPB*27; i += CONV_THREADS) {
        float k = __ldg(wgt + c0*27 + i);
        wpk[i] = pk2(k, k);
    }
    // zero halos of both channel buffers
    for (int i = tid; i < 2*HS*DS; i += CONV_THREADS) {
        int b   = i / (HS*DS);
        int rr  = i - b*(HS*DS);
        int shy = rr / DS, sdd = rr % DS;
        __half* row = &slabH[b][shy][sdd][0];
        *reinterpret_cast<unsigned int*>(row)       = 0u;
        *reinterpret_cast<unsigned int*>(row + 162) = 0u;
        *reinterpret_cast<unsigned int*>(row + 164) = 0u;
        *reinterpret_cast<unsigned int*>(row + 166) = 0u;
    }

    unsigned long long A[DT][2];
    #pragma unroll
    for (int od = 0; od < DT; od++) { A[od][0] = 0ull; A[od][1] = 0ull; }

    #pragma unroll 1
    for (int cp = 0; cp < CPB/2; cp++) {
        __syncthreads();

        // ---- fill 2 channels: 12 independent LDG.128 (high MLP) ----
        #pragma unroll
        for (int ch = 0; ch < 2; ch++) {
            const __half* __restrict__ vc = g_varH + (size_t)(c0 + cp*2 + ch) * DHWSZ;
            #pragma unroll
            for (int r = 0; r < 6; r++) {
                int idx = r*CONV_THREADS + tid;          // 0..959
                int row = idx / 20;                      // 0..47
                int w8  = (idx % 20) * 8;
                int shy = row / DS;                      // 0..5
                int sdd = row - shy*DS;                  // 0..7
                int dd  = d0 - 1 + sdd;
                int hy  = h0 - 1 + shy;
                uint4 v = make_uint4(0u, 0u, 0u, 0u);
                if (dd >= 0 && dd < DDEP && hy >= 0 && hy < HH)
                    v = *(const uint4*)(vc + (size_t)dd*HWSZ + hy*WW + w8);
                unsigned int* dst = reinterpret_cast<unsigned int*>(&slabH[ch][shy][sdd][2 + w8]);
                dst[0] = v.x; dst[1] = v.y; dst[2] = v.z; dst[3] = v.w;
            }
        }
        __syncthreads();

        // ---- compute both channels ----
        #pragma unroll
        for (int ch = 0; ch < 2; ch++) {
            const unsigned long long* wc = wpk + (cp*2 + ch)*27;
            #pragma unroll
            for (int dy = 0; dy < 3; dy++) {
                unsigned long long k00 = wc[(0*3+dy)*3+0], k01 = wc[(0*3+dy)*3+1], k02 = wc[(0*3+dy)*3+2];
                unsigned long long k10 = wc[(1*3+dy)*3+0], k11 = wc[(1*3+dy)*3+1], k12 = wc[(1*3+dy)*3+2];
                unsigned long long k20 = wc[(2*3+dy)*3+0], k21 = wc[(2*3+dy)*3+1], k22 = wc[(2*3+dy)*3+2];
                const __half* hrow = &slabH[ch][hl + dy][0][0];
                #pragma unroll
                for (int sdd = 0; sdd < DS; sdd++) {
                    const __half* col = hrow + sdd*WPH;
                    uint2 u0 = *(const uint2*)(col + w0);       // (v-2,v-1),(v0,v1)
                    uint2 u1 = *(const uint2*)(col + w0 + 4);   // (v2,v3),(v4,v5)
                    float2 fA = __half22float2(u2h(u0.x));
                    float2 fB = __half22float2(u2h(u0.y));
                    float2 fC = __half22float2(u2h(u1.x));
                    float2 fD = __half22float2(u2h(u1.y));
                    unsigned long long P0 = pk2(fA.y, fB.x);    // (v-1,v0)
                    unsigned long long P1 = pk2(fB.x, fB.y);    // (v0,v1)
                    unsigned long long P2 = pk2(fB.y, fC.x);    // (v1,v2)
                    unsigned long long P3 = pk2(fC.x, fC.y);    // (v2,v3)
                    unsigned long long P4 = pk2(fC.y, fD.x);    // (v3,v4)
                    #pragma unroll
                    for (int dz = 0; dz < 3; dz++) {
                        int od = sdd - dz;
                        if (od < 0 || od >= DT) continue;
                        unsigned long long q0 = (dz==0) ? k00 : (dz==1) ? k10 : k20;
                        unsigned long long q1 = (dz==0) ? k01 : (dz==1) ? k11 : k21;
                        unsigned long long q2 = (dz==0) ? k02 : (dz==1) ? k12 : k22;
                        A[od][0] = fma2(P0, q0, A[od][0]);
                        A[od][0] = fma2(P1, q1, A[od][0]);
                        A[od][0] = fma2(P2, q2, A[od][0]);
                        A[od][1] = fma2(P2, q0, A[od][1]);
                        A[od][1] = fma2(P3, q1, A[od][1]);
                        A[od][1] = fma2(P4, q2, A[od][1]);
                    }
                }
            }
        }
    }

    const int ob = (h0 + hl)*WW + w0;
    #pragma unroll
    for (int od = 0; od < DT; od++) {
        float o0, o1, o2, o3;
        upk2(A[od][0], o0, o1);
        upk2(A[od][1], o2, o3);
        float4 v = make_float4(o0, o1, o2, o3);
        *(float4*)(outbuf + (size_t)(d0 + od)*HWSZ + ob) = v;
    }
}

// ---------------- kernel 4: softmax / depth / confidence --------------------
__global__ void __launch_bounds__(128) k_post(const float* __restrict__ dv,
                                              float* __restrict__ out) {
    int pix = blockIdx.x * 128 + threadIdx.x;
    float p[DDEP];
    float mx = -1e30f;
    #pragma unroll
    for (int d = 0; d < DDEP; d++) {
        size_t o = (size_t)d*HWSZ + pix;
        p[d] = (g_costp[0][o] + g_costp[1][o]) + (g_costp[2][o] + g_costp[3][o]);
        mx = fmaxf(mx, p[d]);
    }
    float s = 0.0f;
    #pragma unroll
    for (int d = 0; d < DDEP; d++) { p[d] = expf(p[d] - mx); s += p[d]; }
    float inv = 1.0f / s;
    float depth = 0.0f, didx = 0.0f;
    #pragma unroll
    for (int d = 0; d < DDEP; d++) {
        float pr = p[d] * inv;
        p[d] = pr;
        depth += pr * __ldg(dv + d);
        didx  += pr * (float)d;
    }
    int di = (int)didx;
    di = min(max(di, 0), DDEP - 1);
    float conf = 0.0f;
    #pragma unroll
    for (int d = 0; d < DDEP; d++) {
        bool inwin = (d >= di - 1) && (d <= di + 2);
        conf += inwin ? p[d] : 0.0f;
    }
    out[pix]        = depth;
    out[HWSZ + pix] = conf;
}

// ---------------- launcher ---------------------------------------------------
extern "C" void kernel_launch(void* const* d_in, const int* in_sizes, int n_in,
                              void* d_out, int out_size) {
    const float* features = nullptr;
    const float* pm       = nullptr;
    const float* dv       = nullptr;
    const float* wgt      = nullptr;
    for (int i = 0; i < n_in; i++) {
        switch (in_sizes[i]) {
            case NV*CC*HWSZ: features = (const float*)d_in[i]; break;
            case 160:        pm       = (const float*)d_in[i]; break;
            case 48:         dv       = (const float*)d_in[i]; break;
            case 864:        wgt      = (const float*)d_in[i]; break;
            default: break;
        }
    }
    if (!features) features = (const float*)d_in[0];
    if (!pm)       pm       = (const float*)d_in[1];
    if (!dv)       dv       = (const float*)d_in[2];
    if (!wgt)      wgt      = (const float*)d_in[3];
    float* out = (float*)d_out;

    k_setup<<<1, 32>>>(pm);
    k_transpose<<<dim3(HWSZ/128, NV), 1024>>>(features);
    k_var<<<DHWSZ/128, 128>>>(dv);
    k_conv<<<dim3(HH/HT, DDEP/DT, CSPLIT), CONV_THREADS>>>(wgt);
    k_post<<<HWSZ/128, 128>>>(dv, out);
}